// round 14
// baseline (speedup 1.0000x reference)
#include <cuda_runtime.h>
#include <cuda_bf16.h>
#include <mma.h>

using namespace nvcuda;

// Problem constants (fixed by reference)
#define Bc   2
#define Sc   2048
#define Dc   1024
#define Hc   16
#define DKc  64
#define FFc  4096
#define Mc   (Bc*Sc)          // 4096 rows
#define EPSc 1e-5f

// ---------------------------------------------------------------------------
// Scratch (no cudaMalloc allowed -> __device__ globals)
// ---------------------------------------------------------------------------
__device__ float g_q  [Mc*Dc];
__device__ float g_k  [Mc*Dc];
__device__ float g_v  [Mc*Dc];
__device__ float g_ctx[Mc*Dc];
__device__ float g_t0 [Mc*Dc];
__device__ float g_h  [Mc*Dc];
__device__ float g_ff [Mc*FFc];

// split-store two adjacent fp32 values as bf16 hi/lo pairs
__device__ __forceinline__
void bf16_split_pair(__nv_bfloat16* H, __nv_bfloat16* L, int off,
                     float a, float b)
{
    __nv_bfloat16 h0 = __float2bfloat16(a);
    __nv_bfloat16 h1 = __float2bfloat16(b);
    __nv_bfloat16 l0 = __float2bfloat16(a - __bfloat162float(h0));
    __nv_bfloat16 l1 = __float2bfloat16(b - __bfloat162float(h1));
    __nv_bfloat162 hv; hv.x = h0; hv.y = h1;
    __nv_bfloat162 lv; lv.x = l0; lv.y = l1;
    *(__nv_bfloat162*)(H + off) = hv;
    *(__nv_bfloat162*)(L + off) = lv;
}

// ---------------------------------------------------------------------------
// Split-bf16 ("bf16x3") WMMA SGEMM core: C[M,N] = A[M,K] @ B[K,N] + bias
// a = hi + lo (both bf16); product hi*hi + hi*lo + lo*hi (3 MMAs), dropping
// only lo*lo (<= 2^-18 |ab|) -> rel err ~1e-4, fp32 accumulate.
//   RELU: max(0,.)     RESID: add residual R[row, col]
// BM=BN=128, BK=16, 256 threads = 8 warps (4 row x 2 col), each warp owns a
// 32x64 region = 2x4 m16n16k16 fragments. Double-buffered smem.
// ---------------------------------------------------------------------------
template<bool RELU, bool RESID>
__device__ __forceinline__
void sgemm_core(const float* __restrict__ A, const float* __restrict__ Bm,
                const float* __restrict__ bias, const float* __restrict__ R,
                float* __restrict__ C, int N, int K, int bx, int by)
{
    constexpr int BM = 128, BN = 128, BK = 16;
    constexpr int LDA = 24;    // A tile row pitch (bf16 elems)
    constexpr int LDB = 136;   // B tile row pitch (bf16 elems)
    constexpr int A_BYTES   = BM * LDA * 2;            // 6144
    constexpr int B_BYTES   = BK * LDB * 2;            // 4352
    constexpr int BUF_BYTES = 2*A_BYTES + 2*B_BYTES;   // 20992
    __shared__ __align__(32) char smem_raw[2*BUF_BYTES];   // 41984 B

    const int tid = threadIdx.x;
    const int w   = tid >> 5;
    const int wr  = w >> 1;        // 0..3
    const int wc  = w & 1;         // 0..1

    const int aRow0 = (tid*2)     >> 2, aCol0 = ((tid*2)     & 3) * 4;
    const int aRow1 = (tid*2 + 1) >> 2, aCol1 = ((tid*2 + 1) & 3) * 4;
    const int bRow0 = (tid*2)     >> 5, bCol0 = ((tid*2)     & 31) * 4;
    const int bRow1 = (tid*2 + 1) >> 5, bCol1 = ((tid*2 + 1) & 31) * 4;

    const float* Ab = A + (size_t)by * BM * K;
    const float* Bb = Bm + bx * BN;

    wmma::fragment<wmma::accumulator, 16, 16, 16, float> cacc[2][4];
    #pragma unroll
    for (int i = 0; i < 2; i++)
        #pragma unroll
        for (int j = 0; j < 4; j++)
            wmma::fill_fragment(cacc[i][j], 0.0f);

    auto stage = [&](int b, const float4& av0, const float4& av1,
                     const float4& bv0, const float4& bv1) {
        __nv_bfloat16* Ah = (__nv_bfloat16*)(smem_raw + b*BUF_BYTES);
        __nv_bfloat16* Al = Ah + BM*LDA;
        __nv_bfloat16* Bh = (__nv_bfloat16*)(smem_raw + b*BUF_BYTES + 2*A_BYTES);
        __nv_bfloat16* Bl = Bh + BK*LDB;
        bf16_split_pair(Ah, Al, aRow0*LDA + aCol0,     av0.x, av0.y);
        bf16_split_pair(Ah, Al, aRow0*LDA + aCol0 + 2, av0.z, av0.w);
        bf16_split_pair(Ah, Al, aRow1*LDA + aCol1,     av1.x, av1.y);
        bf16_split_pair(Ah, Al, aRow1*LDA + aCol1 + 2, av1.z, av1.w);
        bf16_split_pair(Bh, Bl, bRow0*LDB + bCol0,     bv0.x, bv0.y);
        bf16_split_pair(Bh, Bl, bRow0*LDB + bCol0 + 2, bv0.z, bv0.w);
        bf16_split_pair(Bh, Bl, bRow1*LDB + bCol1,     bv1.x, bv1.y);
        bf16_split_pair(Bh, Bl, bRow1*LDB + bCol1 + 2, bv1.z, bv1.w);
    };

    {   // prologue: slab 0 -> buffer 0
        float4 av0 = *(const float4*)(Ab + (size_t)aRow0 * K + aCol0);
        float4 av1 = *(const float4*)(Ab + (size_t)aRow1 * K + aCol1);
        float4 bv0 = *(const float4*)(Bb + (size_t)bRow0 * N + bCol0);
        float4 bv1 = *(const float4*)(Bb + (size_t)bRow1 * N + bCol1);
        stage(0, av0, av1, bv0, bv1);
    }
    __syncthreads();

    int buf = 0;
    for (int k0 = BK; k0 <= K; k0 += BK) {
        float4 av0, av1, bv0, bv1;
        const bool more = (k0 < K);
        if (more) {
            av0 = *(const float4*)(Ab + (size_t)aRow0 * K + k0 + aCol0);
            av1 = *(const float4*)(Ab + (size_t)aRow1 * K + k0 + aCol1);
            bv0 = *(const float4*)(Bb + (size_t)(k0 + bRow0) * N + bCol0);
            bv1 = *(const float4*)(Bb + (size_t)(k0 + bRow1) * N + bCol1);
        }
        {
            const __nv_bfloat16* Ah = (const __nv_bfloat16*)(smem_raw + buf*BUF_BYTES);
            const __nv_bfloat16* Al = Ah + BM*LDA;
            const __nv_bfloat16* Bh = (const __nv_bfloat16*)(smem_raw + buf*BUF_BYTES + 2*A_BYTES);
            const __nv_bfloat16* Bl = Bh + BK*LDB;

            wmma::fragment<wmma::matrix_a, 16, 16, 16, __nv_bfloat16, wmma::row_major> ah[2], al[2];
            #pragma unroll
            for (int i = 0; i < 2; i++) {
                wmma::load_matrix_sync(ah[i], Ah + (wr*32 + i*16)*LDA, LDA);
                wmma::load_matrix_sync(al[i], Al + (wr*32 + i*16)*LDA, LDA);
            }
            #pragma unroll
            for (int j = 0; j < 4; j++) {
                wmma::fragment<wmma::matrix_b, 16, 16, 16, __nv_bfloat16, wmma::row_major> bh, bl;
                wmma::load_matrix_sync(bh, Bh + wc*64 + j*16, LDB);
                wmma::load_matrix_sync(bl, Bl + wc*64 + j*16, LDB);
                #pragma unroll
                for (int i = 0; i < 2; i++) {
                    wmma::mma_sync(cacc[i][j], ah[i], bh, cacc[i][j]);
                    wmma::mma_sync(cacc[i][j], ah[i], bl, cacc[i][j]);
                    wmma::mma_sync(cacc[i][j], al[i], bh, cacc[i][j]);
                }
            }
        }
        if (more) {
            stage(buf ^ 1, av0, av1, bv0, bv1);
            __syncthreads();
            buf ^= 1;
        }
    }

    // epilogue: frags -> smem (two 64-row halves) -> gmem
    __syncthreads();
    float* Cs = (float*)smem_raw;
    const int colBase = bx * BN;
    const int col     = (tid & 31) * 4;
    const float4 bv   = *(const float4*)(bias + colBase + col);

    #pragma unroll
    for (int half = 0; half < 2; half++) {
        if ((wr >> 1) == half) {
            const int lrb = (wr & 1) * 32;
            #pragma unroll
            for (int i = 0; i < 2; i++)
                #pragma unroll
                for (int j = 0; j < 4; j++)
                    wmma::store_matrix_sync(Cs + (lrb + i*16)*BN + wc*64 + j*16,
                                            cacc[i][j], BN, wmma::mem_row_major);
        }
        __syncthreads();
        #pragma unroll
        for (int it = 0; it < 8; it++) {
            const int rl = (tid >> 5) + it*8;
            const int rg = by*BM + half*64 + rl;
            float4 o = *(float4*)(Cs + rl*BN + col);
            o.x += bv.x; o.y += bv.y; o.z += bv.z; o.w += bv.w;
            if (RESID) {
                float4 rv = *(const float4*)(R + (size_t)rg * N + colBase + col);
                o.x += rv.x; o.y += rv.y; o.z += rv.z; o.w += rv.w;
            }
            if (RELU) {
                o.x = fmaxf(o.x, 0.f); o.y = fmaxf(o.y, 0.f);
                o.z = fmaxf(o.z, 0.f); o.w = fmaxf(o.w, 0.f);
            }
            *(float4*)(C + (size_t)rg * N + colBase + col) = o;
        }
        __syncthreads();
    }
}

template<bool RELU, bool RESID>
__global__ __launch_bounds__(256)
void sgemm_bias(const float* __restrict__ A, const float* __restrict__ Bm,
                const float* __restrict__ bias, const float* __restrict__ R,
                float* __restrict__ C, int N, int K)
{
    sgemm_core<RELU, RESID>(A, Bm, bias, R, C, N, K, blockIdx.x, blockIdx.y);
}

// Fused QKV: one launch, blockIdx.z selects the projection.
__global__ __launch_bounds__(256)
void sgemm_qkv(const float* __restrict__ x,
               const float* __restrict__ Wq, const float* __restrict__ bq,
               const float* __restrict__ Wk, const float* __restrict__ bk,
               const float* __restrict__ Wv, const float* __restrict__ bv,
               float* __restrict__ q, float* __restrict__ k,
               float* __restrict__ v)
{
    const float* W;  const float* bias;  float* C;
    if (blockIdx.z == 0)      { W = Wq; bias = bq; C = q; }
    else if (blockIdx.z == 1) { W = Wk; bias = bk; C = k; }
    else                      { W = Wv; bias = bv; C = v; }
    sgemm_core<false, false>(x, W, bias, nullptr, C, Dc, Dc, blockIdx.x, blockIdx.y);
}

// ---------------------------------------------------------------------------
// Attention scores via bf16x3 WMMA: P[b,h,q,k] = (Q . K)/8, masked.
// B operand = K-tile read as col_major matrix_b over the row-major smem tile.
// K-dim = 64: exactly two BK=32 slabs. Slab 1's global loads are prefetched
// into registers during slab 0's MMA compute (explicit 2-slab pipeline).
// Epilogue stages via smem in two 64-row halves (mask + scale).
// ---------------------------------------------------------------------------
__global__ __launch_bounds__(256)
void attn_scores(const float* __restrict__ Q, const float* __restrict__ Kt,
                 const int* __restrict__ mask, float* __restrict__ P)
{
    constexpr int BM=128, BN=128, BK=32, LDQ=40;   // 32 + 8 pad (mult of 8)
    constexpr int QT = BM*LDQ;                     // elems per matrix
    __shared__ __align__(32) char sm[4*QT*2];      // 40960 B; epilogue reuses

    __nv_bfloat16* Qh = (__nv_bfloat16*)sm;
    __nv_bfloat16* Ql = Qh + QT;
    __nv_bfloat16* Kh = Ql + QT;
    __nv_bfloat16* Kl = Kh + QT;

    const int bh = blockIdx.z;
    const int b  = bh / Hc;
    const int h  = bh % Hc;
    const int tid = threadIdx.x;
    const int w   = tid >> 5;
    const int wr  = w >> 1;        // 0..3
    const int wc  = w & 1;         // 0..1

    const float* Qb = Q  + ((size_t)(b*Sc + blockIdx.y*BM)) * Dc + h*DKc;
    const float* Kb = Kt + ((size_t)(b*Sc + blockIdx.x*BN)) * Dc + h*DKc;

    wmma::fragment<wmma::accumulator, 16, 16, 16, float> cacc[2][4];
    #pragma unroll
    for (int i = 0; i < 2; i++)
        #pragma unroll
        for (int j = 0; j < 4; j++)
            wmma::fill_fragment(cacc[i][j], 0.0f);

    // per-thread tile coordinates (4 float4 per matrix per slab)
    int rr[4], kk[4];
    #pragma unroll
    for (int t = 0; t < 4; t++) {
        int idx = tid + 256*t;        // 0..1023
        rr[t] = idx >> 3;             // 0..127
        kk[t] = (idx & 7) * 4;        // 0,4,...,28
    }

    auto store_slab = [&](const float4* qv, const float4* kv) {
        #pragma unroll
        for (int t = 0; t < 4; t++) {
            bf16_split_pair(Qh, Ql, rr[t]*LDQ + kk[t],     qv[t].x, qv[t].y);
            bf16_split_pair(Qh, Ql, rr[t]*LDQ + kk[t] + 2, qv[t].z, qv[t].w);
            bf16_split_pair(Kh, Kl, rr[t]*LDQ + kk[t],     kv[t].x, kv[t].y);
            bf16_split_pair(Kh, Kl, rr[t]*LDQ + kk[t] + 2, kv[t].z, kv[t].w);
        }
    };

    auto compute_slab = [&]() {
        #pragma unroll
        for (int ks = 0; ks < 2; ks++) {
            wmma::fragment<wmma::matrix_a, 16, 16, 16, __nv_bfloat16, wmma::row_major> ah[2], al[2];
            #pragma unroll
            for (int i = 0; i < 2; i++) {
                wmma::load_matrix_sync(ah[i], Qh + (wr*32 + i*16)*LDQ + ks*16, LDQ);
                wmma::load_matrix_sync(al[i], Ql + (wr*32 + i*16)*LDQ + ks*16, LDQ);
            }
            #pragma unroll
            for (int j = 0; j < 4; j++) {
                wmma::fragment<wmma::matrix_b, 16, 16, 16, __nv_bfloat16, wmma::col_major> bh, bl;
                wmma::load_matrix_sync(bh, Kh + (wc*64 + j*16)*LDQ + ks*16, LDQ);
                wmma::load_matrix_sync(bl, Kl + (wc*64 + j*16)*LDQ + ks*16, LDQ);
                #pragma unroll
                for (int i = 0; i < 2; i++) {
                    wmma::mma_sync(cacc[i][j], ah[i], bh, cacc[i][j]);
                    wmma::mma_sync(cacc[i][j], ah[i], bl, cacc[i][j]);
                    wmma::mma_sync(cacc[i][j], al[i], bh, cacc[i][j]);
                }
            }
        }
    };

    // slab 0: load + store to smem
    {
        float4 qv[4], kv[4];
        #pragma unroll
        for (int t = 0; t < 4; t++) {
            qv[t] = *(const float4*)(Qb + (size_t)rr[t]*Dc + kk[t]);
            kv[t] = *(const float4*)(Kb + (size_t)rr[t]*Dc + kk[t]);
        }
        store_slab(qv, kv);
    }
    __syncthreads();

    // prefetch slab 1 into registers (overlaps with slab-0 MMAs below)
    float4 qv1[4], kv1[4];
    #pragma unroll
    for (int t = 0; t < 4; t++) {
        qv1[t] = *(const float4*)(Qb + (size_t)rr[t]*Dc + BK + kk[t]);
        kv1[t] = *(const float4*)(Kb + (size_t)rr[t]*Dc + BK + kk[t]);
    }

    compute_slab();          // slab 0 (prefetch LDGs in flight)
    __syncthreads();         // all reads of slab-0 tiles done
    store_slab(qv1, kv1);    // overwrite tiles with slab 1
    __syncthreads();
    compute_slab();          // slab 1
    __syncthreads();         // tiles dead; smem reused as Cs below

    // epilogue: scale + mask via smem staging in two 64-row halves
    float* Cs = (float*)sm;
    const float scale   = 0.125f;     // 1/sqrt(64)
    const int   colBase = blockIdx.x * BN;
    const int   col     = (tid & 31) * 4;
    const int4  mk      = *(const int4*)(mask + b*Sc + colBase + col);

    #pragma unroll
    for (int half = 0; half < 2; half++) {
        if ((wr >> 1) == half) {
            const int lrb = (wr & 1) * 32;
            #pragma unroll
            for (int i = 0; i < 2; i++)
                #pragma unroll
                for (int j = 0; j < 4; j++)
                    wmma::store_matrix_sync(Cs + (lrb + i*16)*BN + wc*64 + j*16,
                                            cacc[i][j], BN, wmma::mem_row_major);
        }
        __syncthreads();
        #pragma unroll
        for (int it = 0; it < 8; it++) {
            const int rl  = (tid >> 5) + it*8;
            const int row = blockIdx.y*BM + half*64 + rl;
            float4 o = *(float4*)(Cs + rl*BN + col);
            o.x = (mk.x == 0) ? -1e9f : o.x*scale;
            o.y = (mk.y == 0) ? -1e9f : o.y*scale;
            o.z = (mk.z == 0) ? -1e9f : o.z*scale;
            o.w = (mk.w == 0) ? -1e9f : o.w*scale;
            *(float4*)(P + ((size_t)bh * Sc + row) * Sc + colBase + col) = o;
        }
        __syncthreads();
    }
}

// ---------------------------------------------------------------------------
// Row softmax in-place over S=2048 columns. Warp-shuffle reductions.
// ---------------------------------------------------------------------------
__global__ __launch_bounds__(256)
void softmax_rows(float* __restrict__ P)
{
    __shared__ float wred[8];
    const size_t base = (size_t)blockIdx.x * Sc;
    const int tid  = threadIdx.x;
    const int lane = tid & 31;
    const int wid  = tid >> 5;

    float v[8];
    float4 a = *(float4*)(P + base + tid*8);
    float4 b = *(float4*)(P + base + tid*8 + 4);
    v[0]=a.x; v[1]=a.y; v[2]=a.z; v[3]=a.w;
    v[4]=b.x; v[5]=b.y; v[6]=b.z; v[7]=b.w;

    float m = v[0];
    #pragma unroll
    for (int i = 1; i < 8; i++) m = fmaxf(m, v[i]);
    #pragma unroll
    for (int o = 16; o > 0; o >>= 1) m = fmaxf(m, __shfl_xor_sync(0xffffffffu, m, o));
    if (lane == 0) wred[wid] = m;
    __syncthreads();
    m = wred[0];
    #pragma unroll
    for (int i = 1; i < 8; i++) m = fmaxf(m, wred[i]);
    __syncthreads();

    float sum = 0.f;
    #pragma unroll
    for (int i = 0; i < 8; i++) { v[i] = __expf(v[i] - m); sum += v[i]; }
    #pragma unroll
    for (int o = 16; o > 0; o >>= 1) sum += __shfl_xor_sync(0xffffffffu, sum, o);
    if (lane == 0) wred[wid] = sum;
    __syncthreads();
    sum = wred[0];
    #pragma unroll
    for (int i = 1; i < 8; i++) sum += wred[i];
    const float inv = 1.f / sum;

    float4 o0 = make_float4(v[0]*inv, v[1]*inv, v[2]*inv, v[3]*inv);
    float4 o1 = make_float4(v[4]*inv, v[5]*inv, v[6]*inv, v[7]*inv);
    *(float4*)(P + base + tid*8)     = o0;
    *(float4*)(P + base + tid*8 + 4) = o1;
}

// ---------------------------------------------------------------------------
// ctx = P @ V via bf16x3 WMMA (per-head GEMM, N=64, K=2048).
// BM=128, BK=16, 8 warps in 4x2; each warp 32x32 = 2x2 frags.
// Double-buffered hi/lo smem; epilogue stores frags straight to gmem
// (ldm = Dc = 1024, bases 128B-aligned).
// ---------------------------------------------------------------------------
__global__ __launch_bounds__(256)
void attn_ctx(const float* __restrict__ P, const float* __restrict__ V,
              float* __restrict__ ctx)
{
    constexpr int BM = 128, BN = 64, BK = 16;
    constexpr int LDA = 24;    // P tile row pitch (bf16 elems)
    constexpr int LDB = 72;    // V tile row pitch (bf16 elems; 64 + 8 pad)
    constexpr int A_BYTES   = BM * LDA * 2;            // 6144
    constexpr int B_BYTES   = BK * LDB * 2;            // 2304
    constexpr int BUF_BYTES = 2*A_BYTES + 2*B_BYTES;   // 16896
    __shared__ __align__(32) char smem_raw[2*BUF_BYTES];   // 33792 B

    const int bh = blockIdx.y;
    const int b  = bh / Hc;
    const int h  = bh % Hc;
    const int tid = threadIdx.x;
    const int w   = tid >> 5;
    const int wr  = w >> 1;        // 0..3 : rows wr*32
    const int wc  = w & 1;         // 0..1 : cols wc*32

    const int aRow0 = (tid*2)     >> 2, aCol0 = ((tid*2)     & 3) * 4;
    const int aRow1 = (tid*2 + 1) >> 2, aCol1 = ((tid*2 + 1) & 3) * 4;
    const int vRow  = tid >> 4;          // 0..15
    const int vCol  = (tid & 15) * 4;    // 0..60

    const float* Pb = P + ((size_t)bh * Sc + blockIdx.x * BM) * Sc;
    const float* Vb = V + ((size_t)b * Sc) * Dc + h * DKc;

    wmma::fragment<wmma::accumulator, 16, 16, 16, float> cacc[2][2];
    #pragma unroll
    for (int i = 0; i < 2; i++)
        #pragma unroll
        for (int j = 0; j < 2; j++)
            wmma::fill_fragment(cacc[i][j], 0.0f);

    auto stage = [&](int bsel, const float4& p0, const float4& p1, const float4& vv) {
        __nv_bfloat16* Ah = (__nv_bfloat16*)(smem_raw + bsel*BUF_BYTES);
        __nv_bfloat16* Al = Ah + BM*LDA;
        __nv_bfloat16* Bh = (__nv_bfloat16*)(smem_raw + bsel*BUF_BYTES + 2*A_BYTES);
        __nv_bfloat16* Bl = Bh + BK*LDB;
        bf16_split_pair(Ah, Al, aRow0*LDA + aCol0,     p0.x, p0.y);
        bf16_split_pair(Ah, Al, aRow0*LDA + aCol0 + 2, p0.z, p0.w);
        bf16_split_pair(Ah, Al, aRow1*LDA + aCol1,     p1.x, p1.y);
        bf16_split_pair(Ah, Al, aRow1*LDA + aCol1 + 2, p1.z, p1.w);
        bf16_split_pair(Bh, Bl, vRow*LDB + vCol,       vv.x, vv.y);
        bf16_split_pair(Bh, Bl, vRow*LDB + vCol + 2,   vv.z, vv.w);
    };

    {   // prologue
        float4 p0 = *(const float4*)(Pb + (size_t)aRow0 * Sc + aCol0);
        float4 p1 = *(const float4*)(Pb + (size_t)aRow1 * Sc + aCol1);
        float4 vv = *(const float4*)(Vb + (size_t)vRow * Dc + vCol);
        stage(0, p0, p1, vv);
    }
    __syncthreads();

    int buf = 0;
    for (int k0 = BK; k0 <= Sc; k0 += BK) {
        float4 p0, p1, vv;
        const bool more = (k0 < Sc);
        if (more) {
            p0 = *(const float4*)(Pb + (size_t)aRow0 * Sc + k0 + aCol0);
            p1 = *(const float4*)(Pb + (size_t)aRow1 * Sc + k0 + aCol1);
            vv = *(const float4*)(Vb + (size_t)(k0 + vRow) * Dc + vCol);
        }
        {
            const __nv_bfloat16* Ah = (const __nv_bfloat16*)(smem_raw + buf*BUF_BYTES);
            const __nv_bfloat16* Al = Ah + BM*LDA;
            const __nv_bfloat16* Bh = (const __nv_bfloat16*)(smem_raw + buf*BUF_BYTES + 2*A_BYTES);
            const __nv_bfloat16* Bl = Bh + BK*LDB;

            wmma::fragment<wmma::matrix_a, 16, 16, 16, __nv_bfloat16, wmma::row_major> ah[2], al[2];
            #pragma unroll
            for (int i = 0; i < 2; i++) {
                wmma::load_matrix_sync(ah[i], Ah + (wr*32 + i*16)*LDA, LDA);
                wmma::load_matrix_sync(al[i], Al + (wr*32 + i*16)*LDA, LDA);
            }
            #pragma unroll
            for (int j = 0; j < 2; j++) {
                wmma::fragment<wmma::matrix_b, 16, 16, 16, __nv_bfloat16, wmma::row_major> bh, bl;
                wmma::load_matrix_sync(bh, Bh + wc*32 + j*16, LDB);
                wmma::load_matrix_sync(bl, Bl + wc*32 + j*16, LDB);
                #pragma unroll
                for (int i = 0; i < 2; i++) {
                    wmma::mma_sync(cacc[i][j], ah[i], bh, cacc[i][j]);
                    wmma::mma_sync(cacc[i][j], ah[i], bl, cacc[i][j]);
                    wmma::mma_sync(cacc[i][j], al[i], bh, cacc[i][j]);
                }
            }
        }
        if (more) {
            stage(buf ^ 1, p0, p1, vv);
            __syncthreads();
            buf ^= 1;
        }
    }

    // epilogue: store fragments directly to gmem (row-major, ldm = Dc)
    float* Cg = ctx + ((size_t)(b*Sc + blockIdx.x*BM + wr*32)) * Dc + h*DKc + wc*32;
    #pragma unroll
    for (int i = 0; i < 2; i++)
        #pragma unroll
        for (int j = 0; j < 2; j++)
            wmma::store_matrix_sync(Cg + (size_t)(i*16)*Dc + j*16,
                                    cacc[i][j], Dc, wmma::mem_row_major);
}

// ---------------------------------------------------------------------------
// LayerNorm (single input, residual pre-added by GEMM epilogue)
// ---------------------------------------------------------------------------
__global__ __launch_bounds__(256)
void ln_rows(const float* __restrict__ X,
             const float* __restrict__ g, const float* __restrict__ be,
             float* __restrict__ out)
{
    __shared__ float ws[8], wq[8];
    const size_t base = (size_t)blockIdx.x * Dc;
    const int tid  = threadIdx.x;
    const int lane = tid & 31;
    const int wid  = tid >> 5;

    float v[4];
    float s = 0.f, sq = 0.f;
    #pragma unroll
    for (int t = 0; t < 4; t++) {
        int i = tid + 256*t;
        float val = X[base+i];
        v[t] = val; s += val; sq += val*val;
    }
    #pragma unroll
    for (int o = 16; o > 0; o >>= 1) {
        s  += __shfl_xor_sync(0xffffffffu, s,  o);
        sq += __shfl_xor_sync(0xffffffffu, sq, o);
    }
    if (lane == 0) { ws[wid] = s; wq[wid] = sq; }
    __syncthreads();
    s = ws[0]; sq = wq[0];
    #pragma unroll
    for (int i = 1; i < 8; i++) { s += ws[i]; sq += wq[i]; }

    const float mean = s * (1.f/Dc);
    const float var  = sq * (1.f/Dc) - mean*mean;
    const float inv  = rsqrtf(var + EPSc);
    #pragma unroll
    for (int t = 0; t < 4; t++) {
        int i = tid + 256*t;
        out[base+i] = (v[t] - mean) * inv * g[i] + be[i];
    }
}

// ---------------------------------------------------------------------------
// Launch
// ---------------------------------------------------------------------------
extern "C" void kernel_launch(void* const* d_in, const int* in_sizes, int n_in,
                              void* d_out, int out_size)
{
    const float* x   = (const float*)d_in[0];
    const int*   mask= (const int*)  d_in[1];
    const float* Wq  = (const float*)d_in[2];  const float* bq = (const float*)d_in[3];
    const float* Wk  = (const float*)d_in[4];  const float* bk = (const float*)d_in[5];
    const float* Wv  = (const float*)d_in[6];  const float* bv = (const float*)d_in[7];
    const float* Wo  = (const float*)d_in[8];  const float* bo = (const float*)d_in[9];
    const float* g1  = (const float*)d_in[10]; const float* be1= (const float*)d_in[11];
    const float* W1  = (const float*)d_in[12]; const float* b1 = (const float*)d_in[13];
    const float* W2  = (const float*)d_in[14]; const float* b2 = (const float*)d_in[15];
    const float* g2  = (const float*)d_in[16]; const float* be2= (const float*)d_in[17];

    float* out   = (float*)d_out;
    float* attnP = out + (size_t)Mc * Dc;   // attention probs region of d_out

    float *q, *k, *v, *ctx, *t0, *hbuf, *ff;
    cudaGetSymbolAddress((void**)&q,    g_q);
    cudaGetSymbolAddress((void**)&k,    g_k);
    cudaGetSymbolAddress((void**)&v,    g_v);
    cudaGetSymbolAddress((void**)&ctx,  g_ctx);
    cudaGetSymbolAddress((void**)&t0,   g_t0);
    cudaGetSymbolAddress((void**)&hbuf, g_h);
    cudaGetSymbolAddress((void**)&ff,   g_ff);

    dim3 gD  (Dc/128,  Mc/128);      // N=1024 gemms
    dim3 gQKV(Dc/128,  Mc/128, 3);   // fused QKV
    dim3 gFF (FFc/128, Mc/128);      // N=4096 gemm

    // QKV projections (single launch, z-indexed, bf16x3 tensor path)
    sgemm_qkv<<<gQKV, 256>>>(x, Wq, bq, Wk, bk, Wv, bv, q, k, v);

    // scores -> d_out attn region (raw, bf16x3 tensor path), softmax in-place
    attn_scores<<<dim3(Sc/128, Sc/128, Bc*Hc), 256>>>(q, k, mask, attnP);
    softmax_rows<<<Bc*Hc*Sc, 256>>>(attnP);

    // ctx = attn @ V (bf16x3 tensor path)
    attn_ctx<<<dim3(Sc/128, Bc*Hc), 256>>>(attnP, v, ctx);

    // output projection + residual (fused) -> t0 = ctx@Wo + bo + x, then LN
    sgemm_bias<false, true ><<<gD, 256>>>(ctx, Wo, bo, x, t0, Dc, Dc);
    ln_rows<<<Mc, 256>>>(t0, g1, be1, hbuf);

    // FFN: ff = relu(h@W1 + b1); t0 = ff@W2 + b2 + h (fused residual); LN
    sgemm_bias<true,  false><<<gFF, 256>>>(hbuf, W1, b1, nullptr, ff, FFc, Dc);
    sgemm_bias<false, true ><<<gD, 256>>>(ff,   W2, b2, hbuf,    t0, Dc, FFc);
    ln_rows<<<Mc, 256>>>(t0, g2, be2, out);
}

// round 17
// speedup vs baseline: 1.1647x; 1.1647x over previous
#include <cuda_runtime.h>
#include <cuda_bf16.h>
#include <mma.h>

using namespace nvcuda;

// Problem constants (fixed by reference)
#define Bc   2
#define Sc   2048
#define Dc   1024
#define Hc   16
#define DKc  64
#define FFc  4096
#define Mc   (Bc*Sc)          // 4096 rows
#define EPSc 1e-5f

// ---------------------------------------------------------------------------
// Scratch (no cudaMalloc allowed -> __device__ globals)
// ---------------------------------------------------------------------------
__device__ float g_q  [Mc*Dc];
__device__ float g_k  [Mc*Dc];
__device__ float g_v  [Mc*Dc];
__device__ float g_ctx[Mc*Dc];
__device__ float g_t0 [Mc*Dc];
__device__ float g_h  [Mc*Dc];
__device__ float g_ff [Mc*FFc];

// split-store two adjacent fp32 values as bf16 hi/lo pairs
__device__ __forceinline__
void bf16_split_pair(__nv_bfloat16* H, __nv_bfloat16* L, int off,
                     float a, float b)
{
    __nv_bfloat16 h0 = __float2bfloat16(a);
    __nv_bfloat16 h1 = __float2bfloat16(b);
    __nv_bfloat16 l0 = __float2bfloat16(a - __bfloat162float(h0));
    __nv_bfloat16 l1 = __float2bfloat16(b - __bfloat162float(h1));
    __nv_bfloat162 hv; hv.x = h0; hv.y = h1;
    __nv_bfloat162 lv; lv.x = l0; lv.y = l1;
    *(__nv_bfloat162*)(H + off) = hv;
    *(__nv_bfloat162*)(L + off) = lv;
}

// ---------------------------------------------------------------------------
// Split-bf16 ("bf16x3") WMMA SGEMM core: C[M,N] = A[M,K] @ B[K,N] + bias
// Term-major MMA issue order: for each b-fragment pair, all accumulators see
// (ah*bh), then (ah*bl), then (al*bh) -> same-acc RAW gap = 4 independent
// MMAs, covering HMMA accumulation latency (ncu showed tensor=25% with the
// old 0-gap order).
// ---------------------------------------------------------------------------
template<bool RELU, bool RESID>
__device__ __forceinline__
void sgemm_core(const float* __restrict__ A, const float* __restrict__ Bm,
                const float* __restrict__ bias, const float* __restrict__ R,
                float* __restrict__ C, int N, int K, int bx, int by)
{
    constexpr int BM = 128, BN = 128, BK = 16;
    constexpr int LDA = 24;    // A tile row pitch (bf16 elems)
    constexpr int LDB = 136;   // B tile row pitch (bf16 elems)
    constexpr int A_BYTES   = BM * LDA * 2;            // 6144
    constexpr int B_BYTES   = BK * LDB * 2;            // 4352
    constexpr int BUF_BYTES = 2*A_BYTES + 2*B_BYTES;   // 20992
    __shared__ __align__(32) char smem_raw[2*BUF_BYTES];   // 41984 B

    const int tid = threadIdx.x;
    const int w   = tid >> 5;
    const int wr  = w >> 1;        // 0..3
    const int wc  = w & 1;         // 0..1

    const int aRow0 = (tid*2)     >> 2, aCol0 = ((tid*2)     & 3) * 4;
    const int aRow1 = (tid*2 + 1) >> 2, aCol1 = ((tid*2 + 1) & 3) * 4;
    const int bRow0 = (tid*2)     >> 5, bCol0 = ((tid*2)     & 31) * 4;
    const int bRow1 = (tid*2 + 1) >> 5, bCol1 = ((tid*2 + 1) & 31) * 4;

    const float* Ab = A + (size_t)by * BM * K;
    const float* Bb = Bm + bx * BN;

    wmma::fragment<wmma::accumulator, 16, 16, 16, float> cacc[2][4];
    #pragma unroll
    for (int i = 0; i < 2; i++)
        #pragma unroll
        for (int j = 0; j < 4; j++)
            wmma::fill_fragment(cacc[i][j], 0.0f);

    auto stage = [&](int b, const float4& av0, const float4& av1,
                     const float4& bv0, const float4& bv1) {
        __nv_bfloat16* Ah = (__nv_bfloat16*)(smem_raw + b*BUF_BYTES);
        __nv_bfloat16* Al = Ah + BM*LDA;
        __nv_bfloat16* Bh = (__nv_bfloat16*)(smem_raw + b*BUF_BYTES + 2*A_BYTES);
        __nv_bfloat16* Bl = Bh + BK*LDB;
        bf16_split_pair(Ah, Al, aRow0*LDA + aCol0,     av0.x, av0.y);
        bf16_split_pair(Ah, Al, aRow0*LDA + aCol0 + 2, av0.z, av0.w);
        bf16_split_pair(Ah, Al, aRow1*LDA + aCol1,     av1.x, av1.y);
        bf16_split_pair(Ah, Al, aRow1*LDA + aCol1 + 2, av1.z, av1.w);
        bf16_split_pair(Bh, Bl, bRow0*LDB + bCol0,     bv0.x, bv0.y);
        bf16_split_pair(Bh, Bl, bRow0*LDB + bCol0 + 2, bv0.z, bv0.w);
        bf16_split_pair(Bh, Bl, bRow1*LDB + bCol1,     bv1.x, bv1.y);
        bf16_split_pair(Bh, Bl, bRow1*LDB + bCol1 + 2, bv1.z, bv1.w);
    };

    {   // prologue: slab 0 -> buffer 0
        float4 av0 = *(const float4*)(Ab + (size_t)aRow0 * K + aCol0);
        float4 av1 = *(const float4*)(Ab + (size_t)aRow1 * K + aCol1);
        float4 bv0 = *(const float4*)(Bb + (size_t)bRow0 * N + bCol0);
        float4 bv1 = *(const float4*)(Bb + (size_t)bRow1 * N + bCol1);
        stage(0, av0, av1, bv0, bv1);
    }
    __syncthreads();

    int buf = 0;
    for (int k0 = BK; k0 <= K; k0 += BK) {
        float4 av0, av1, bv0, bv1;
        const bool more = (k0 < K);
        if (more) {
            av0 = *(const float4*)(Ab + (size_t)aRow0 * K + k0 + aCol0);
            av1 = *(const float4*)(Ab + (size_t)aRow1 * K + k0 + aCol1);
            bv0 = *(const float4*)(Bb + (size_t)(k0 + bRow0) * N + bCol0);
            bv1 = *(const float4*)(Bb + (size_t)(k0 + bRow1) * N + bCol1);
        }
        {
            const __nv_bfloat16* Ah = (const __nv_bfloat16*)(smem_raw + buf*BUF_BYTES);
            const __nv_bfloat16* Al = Ah + BM*LDA;
            const __nv_bfloat16* Bh = (const __nv_bfloat16*)(smem_raw + buf*BUF_BYTES + 2*A_BYTES);
            const __nv_bfloat16* Bl = Bh + BK*LDB;

            wmma::fragment<wmma::matrix_a, 16, 16, 16, __nv_bfloat16, wmma::row_major> ah[2], al[2];
            #pragma unroll
            for (int i = 0; i < 2; i++) {
                wmma::load_matrix_sync(ah[i], Ah + (wr*32 + i*16)*LDA, LDA);
                wmma::load_matrix_sync(al[i], Al + (wr*32 + i*16)*LDA, LDA);
            }
            #pragma unroll
            for (int jp = 0; jp < 2; jp++) {
                wmma::fragment<wmma::matrix_b, 16, 16, 16, __nv_bfloat16, wmma::row_major> bh[2], bl[2];
                #pragma unroll
                for (int jj = 0; jj < 2; jj++) {
                    wmma::load_matrix_sync(bh[jj], Bh + wc*64 + (jp*2+jj)*16, LDB);
                    wmma::load_matrix_sync(bl[jj], Bl + wc*64 + (jp*2+jj)*16, LDB);
                }
                // term-major: 4 independent accs between same-acc reuse
                #pragma unroll
                for (int jj = 0; jj < 2; jj++)
                    #pragma unroll
                    for (int i = 0; i < 2; i++)
                        wmma::mma_sync(cacc[i][jp*2+jj], ah[i], bh[jj], cacc[i][jp*2+jj]);
                #pragma unroll
                for (int jj = 0; jj < 2; jj++)
                    #pragma unroll
                    for (int i = 0; i < 2; i++)
                        wmma::mma_sync(cacc[i][jp*2+jj], ah[i], bl[jj], cacc[i][jp*2+jj]);
                #pragma unroll
                for (int jj = 0; jj < 2; jj++)
                    #pragma unroll
                    for (int i = 0; i < 2; i++)
                        wmma::mma_sync(cacc[i][jp*2+jj], al[i], bh[jj], cacc[i][jp*2+jj]);
            }
        }
        if (more) {
            stage(buf ^ 1, av0, av1, bv0, bv1);
            __syncthreads();
            buf ^= 1;
        }
    }

    // epilogue: frags -> smem (two 64-row halves) -> gmem
    __syncthreads();
    float* Cs = (float*)smem_raw;
    const int colBase = bx * BN;
    const int col     = (tid & 31) * 4;
    const float4 bv   = *(const float4*)(bias + colBase + col);

    #pragma unroll
    for (int half = 0; half < 2; half++) {
        if ((wr >> 1) == half) {
            const int lrb = (wr & 1) * 32;
            #pragma unroll
            for (int i = 0; i < 2; i++)
                #pragma unroll
                for (int j = 0; j < 4; j++)
                    wmma::store_matrix_sync(Cs + (lrb + i*16)*BN + wc*64 + j*16,
                                            cacc[i][j], BN, wmma::mem_row_major);
        }
        __syncthreads();
        #pragma unroll
        for (int it = 0; it < 8; it++) {
            const int rl = (tid >> 5) + it*8;
            const int rg = by*BM + half*64 + rl;
            float4 o = *(float4*)(Cs + rl*BN + col);
            o.x += bv.x; o.y += bv.y; o.z += bv.z; o.w += bv.w;
            if (RESID) {
                float4 rv = *(const float4*)(R + (size_t)rg * N + colBase + col);
                o.x += rv.x; o.y += rv.y; o.z += rv.z; o.w += rv.w;
            }
            if (RELU) {
                o.x = fmaxf(o.x, 0.f); o.y = fmaxf(o.y, 0.f);
                o.z = fmaxf(o.z, 0.f); o.w = fmaxf(o.w, 0.f);
            }
            *(float4*)(C + (size_t)rg * N + colBase + col) = o;
        }
        __syncthreads();
    }
}

template<bool RELU, bool RESID>
__global__ __launch_bounds__(256)
void sgemm_bias(const float* __restrict__ A, const float* __restrict__ Bm,
                const float* __restrict__ bias, const float* __restrict__ R,
                float* __restrict__ C, int N, int K)
{
    sgemm_core<RELU, RESID>(A, Bm, bias, R, C, N, K, blockIdx.x, blockIdx.y);
}

// Fused QKV: one launch, blockIdx.z selects the projection.
__global__ __launch_bounds__(256)
void sgemm_qkv(const float* __restrict__ x,
               const float* __restrict__ Wq, const float* __restrict__ bq,
               const float* __restrict__ Wk, const float* __restrict__ bk,
               const float* __restrict__ Wv, const float* __restrict__ bv,
               float* __restrict__ q, float* __restrict__ k,
               float* __restrict__ v)
{
    const float* W;  const float* bias;  float* C;
    if (blockIdx.z == 0)      { W = Wq; bias = bq; C = q; }
    else if (blockIdx.z == 1) { W = Wk; bias = bk; C = k; }
    else                      { W = Wv; bias = bv; C = v; }
    sgemm_core<false, false>(x, W, bias, nullptr, C, Dc, Dc, blockIdx.x, blockIdx.y);
}

// ---------------------------------------------------------------------------
// Attention scores via bf16x3 WMMA: P[b,h,q,k] = (Q . K)/8, masked.
// Two BK=32 slabs with register prefetch of slab 1; term-major MMA order.
// ---------------------------------------------------------------------------
__global__ __launch_bounds__(256)
void attn_scores(const float* __restrict__ Q, const float* __restrict__ Kt,
                 const int* __restrict__ mask, float* __restrict__ P)
{
    constexpr int BM=128, BN=128, BK=32, LDQ=40;   // 32 + 8 pad (mult of 8)
    constexpr int QT = BM*LDQ;                     // elems per matrix
    __shared__ __align__(32) char sm[4*QT*2];      // 40960 B; epilogue reuses

    __nv_bfloat16* Qh = (__nv_bfloat16*)sm;
    __nv_bfloat16* Ql = Qh + QT;
    __nv_bfloat16* Kh = Ql + QT;
    __nv_bfloat16* Kl = Kh + QT;

    const int bh_ = blockIdx.z;
    const int b  = bh_ / Hc;
    const int h  = bh_ % Hc;
    const int tid = threadIdx.x;
    const int w   = tid >> 5;
    const int wr  = w >> 1;        // 0..3
    const int wc  = w & 1;         // 0..1

    const float* Qb = Q  + ((size_t)(b*Sc + blockIdx.y*BM)) * Dc + h*DKc;
    const float* Kb = Kt + ((size_t)(b*Sc + blockIdx.x*BN)) * Dc + h*DKc;

    wmma::fragment<wmma::accumulator, 16, 16, 16, float> cacc[2][4];
    #pragma unroll
    for (int i = 0; i < 2; i++)
        #pragma unroll
        for (int j = 0; j < 4; j++)
            wmma::fill_fragment(cacc[i][j], 0.0f);

    // per-thread tile coordinates (4 float4 per matrix per slab)
    int rr[4], kk[4];
    #pragma unroll
    for (int t = 0; t < 4; t++) {
        int idx = tid + 256*t;        // 0..1023
        rr[t] = idx >> 3;             // 0..127
        kk[t] = (idx & 7) * 4;        // 0,4,...,28
    }

    auto store_slab = [&](const float4* qv, const float4* kv) {
        #pragma unroll
        for (int t = 0; t < 4; t++) {
            bf16_split_pair(Qh, Ql, rr[t]*LDQ + kk[t],     qv[t].x, qv[t].y);
            bf16_split_pair(Qh, Ql, rr[t]*LDQ + kk[t] + 2, qv[t].z, qv[t].w);
            bf16_split_pair(Kh, Kl, rr[t]*LDQ + kk[t],     kv[t].x, kv[t].y);
            bf16_split_pair(Kh, Kl, rr[t]*LDQ + kk[t] + 2, kv[t].z, kv[t].w);
        }
    };

    auto compute_slab = [&]() {
        #pragma unroll
        for (int ks = 0; ks < 2; ks++) {
            wmma::fragment<wmma::matrix_a, 16, 16, 16, __nv_bfloat16, wmma::row_major> ah[2], al[2];
            #pragma unroll
            for (int i = 0; i < 2; i++) {
                wmma::load_matrix_sync(ah[i], Qh + (wr*32 + i*16)*LDQ + ks*16, LDQ);
                wmma::load_matrix_sync(al[i], Ql + (wr*32 + i*16)*LDQ + ks*16, LDQ);
            }
            #pragma unroll
            for (int jp = 0; jp < 2; jp++) {
                wmma::fragment<wmma::matrix_b, 16, 16, 16, __nv_bfloat16, wmma::col_major> bh[2], bl[2];
                #pragma unroll
                for (int jj = 0; jj < 2; jj++) {
                    wmma::load_matrix_sync(bh[jj], Kh + (wc*64 + (jp*2+jj)*16)*LDQ + ks*16, LDQ);
                    wmma::load_matrix_sync(bl[jj], Kl + (wc*64 + (jp*2+jj)*16)*LDQ + ks*16, LDQ);
                }
                #pragma unroll
                for (int jj = 0; jj < 2; jj++)
                    #pragma unroll
                    for (int i = 0; i < 2; i++)
                        wmma::mma_sync(cacc[i][jp*2+jj], ah[i], bh[jj], cacc[i][jp*2+jj]);
                #pragma unroll
                for (int jj = 0; jj < 2; jj++)
                    #pragma unroll
                    for (int i = 0; i < 2; i++)
                        wmma::mma_sync(cacc[i][jp*2+jj], ah[i], bl[jj], cacc[i][jp*2+jj]);
                #pragma unroll
                for (int jj = 0; jj < 2; jj++)
                    #pragma unroll
                    for (int i = 0; i < 2; i++)
                        wmma::mma_sync(cacc[i][jp*2+jj], al[i], bh[jj], cacc[i][jp*2+jj]);
            }
        }
    };

    // slab 0: load + store to smem
    {
        float4 qv[4], kv[4];
        #pragma unroll
        for (int t = 0; t < 4; t++) {
            qv[t] = *(const float4*)(Qb + (size_t)rr[t]*Dc + kk[t]);
            kv[t] = *(const float4*)(Kb + (size_t)rr[t]*Dc + kk[t]);
        }
        store_slab(qv, kv);
    }
    __syncthreads();

    // prefetch slab 1 into registers (overlaps with slab-0 MMAs below)
    float4 qv1[4], kv1[4];
    #pragma unroll
    for (int t = 0; t < 4; t++) {
        qv1[t] = *(const float4*)(Qb + (size_t)rr[t]*Dc + BK + kk[t]);
        kv1[t] = *(const float4*)(Kb + (size_t)rr[t]*Dc + BK + kk[t]);
    }

    compute_slab();          // slab 0 (prefetch LDGs in flight)
    __syncthreads();
    store_slab(qv1, kv1);
    __syncthreads();
    compute_slab();          // slab 1
    __syncthreads();         // tiles dead; smem reused as Cs below

    // epilogue: scale + mask via smem staging in two 64-row halves
    float* Cs = (float*)sm;
    const float scale   = 0.125f;     // 1/sqrt(64)
    const int   colBase = blockIdx.x * BN;
    const int   col     = (tid & 31) * 4;
    const int4  mk      = *(const int4*)(mask + b*Sc + colBase + col);

    #pragma unroll
    for (int half = 0; half < 2; half++) {
        if ((wr >> 1) == half) {
            const int lrb = (wr & 1) * 32;
            #pragma unroll
            for (int i = 0; i < 2; i++)
                #pragma unroll
                for (int j = 0; j < 4; j++)
                    wmma::store_matrix_sync(Cs + (lrb + i*16)*BN + wc*64 + j*16,
                                            cacc[i][j], BN, wmma::mem_row_major);
        }
        __syncthreads();
        #pragma unroll
        for (int it = 0; it < 8; it++) {
            const int rl  = (tid >> 5) + it*8;
            const int row = blockIdx.y*BM + half*64 + rl;
            float4 o = *(float4*)(Cs + rl*BN + col);
            o.x = (mk.x == 0) ? -1e9f : o.x*scale;
            o.y = (mk.y == 0) ? -1e9f : o.y*scale;
            o.z = (mk.z == 0) ? -1e9f : o.z*scale;
            o.w = (mk.w == 0) ? -1e9f : o.w*scale;
            *(float4*)(P + ((size_t)bh_ * Sc + row) * Sc + colBase + col) = o;
        }
        __syncthreads();
    }
}

// ---------------------------------------------------------------------------
// Row softmax in-place over S=2048 columns. Warp-shuffle reductions.
// ---------------------------------------------------------------------------
__global__ __launch_bounds__(256)
void softmax_rows(float* __restrict__ P)
{
    __shared__ float wred[8];
    const size_t base = (size_t)blockIdx.x * Sc;
    const int tid  = threadIdx.x;
    const int lane = tid & 31;
    const int wid  = tid >> 5;

    float v[8];
    float4 a = *(float4*)(P + base + tid*8);
    float4 b = *(float4*)(P + base + tid*8 + 4);
    v[0]=a.x; v[1]=a.y; v[2]=a.z; v[3]=a.w;
    v[4]=b.x; v[5]=b.y; v[6]=b.z; v[7]=b.w;

    float m = v[0];
    #pragma unroll
    for (int i = 1; i < 8; i++) m = fmaxf(m, v[i]);
    #pragma unroll
    for (int o = 16; o > 0; o >>= 1) m = fmaxf(m, __shfl_xor_sync(0xffffffffu, m, o));
    if (lane == 0) wred[wid] = m;
    __syncthreads();
    m = wred[0];
    #pragma unroll
    for (int i = 1; i < 8; i++) m = fmaxf(m, wred[i]);
    __syncthreads();

    float sum = 0.f;
    #pragma unroll
    for (int i = 0; i < 8; i++) { v[i] = __expf(v[i] - m); sum += v[i]; }
    #pragma unroll
    for (int o = 16; o > 0; o >>= 1) sum += __shfl_xor_sync(0xffffffffu, sum, o);
    if (lane == 0) wred[wid] = sum;
    __syncthreads();
    sum = wred[0];
    #pragma unroll
    for (int i = 1; i < 8; i++) sum += wred[i];
    const float inv = 1.f / sum;

    float4 o0 = make_float4(v[0]*inv, v[1]*inv, v[2]*inv, v[3]*inv);
    float4 o1 = make_float4(v[4]*inv, v[5]*inv, v[6]*inv, v[7]*inv);
    *(float4*)(P + base + tid*8)     = o0;
    *(float4*)(P + base + tid*8 + 4) = o1;
}

// ---------------------------------------------------------------------------
// ctx = P @ V via bf16x3 WMMA (per-head GEMM, N=64, K=2048).
// Term-major MMA order: 4 independent accumulators between same-acc reuse.
// ---------------------------------------------------------------------------
__global__ __launch_bounds__(256)
void attn_ctx(const float* __restrict__ P, const float* __restrict__ V,
              float* __restrict__ ctx)
{
    constexpr int BM = 128, BN = 64, BK = 16;
    constexpr int LDA = 24;    // P tile row pitch (bf16 elems)
    constexpr int LDB = 72;    // V tile row pitch (bf16 elems; 64 + 8 pad)
    constexpr int A_BYTES   = BM * LDA * 2;            // 6144
    constexpr int B_BYTES   = BK * LDB * 2;            // 2304
    constexpr int BUF_BYTES = 2*A_BYTES + 2*B_BYTES;   // 16896
    __shared__ __align__(32) char smem_raw[2*BUF_BYTES];   // 33792 B

    const int bh_ = blockIdx.y;
    const int b  = bh_ / Hc;
    const int h  = bh_ % Hc;
    const int tid = threadIdx.x;
    const int w   = tid >> 5;
    const int wr  = w >> 1;        // 0..3 : rows wr*32
    const int wc  = w & 1;         // 0..1 : cols wc*32

    const int aRow0 = (tid*2)     >> 2, aCol0 = ((tid*2)     & 3) * 4;
    const int aRow1 = (tid*2 + 1) >> 2, aCol1 = ((tid*2 + 1) & 3) * 4;
    const int vRow  = tid >> 4;          // 0..15
    const int vCol  = (tid & 15) * 4;    // 0..60

    const float* Pb = P + ((size_t)bh_ * Sc + blockIdx.x * BM) * Sc;
    const float* Vb = V + ((size_t)b * Sc) * Dc + h * DKc;

    wmma::fragment<wmma::accumulator, 16, 16, 16, float> cacc[2][2];
    #pragma unroll
    for (int i = 0; i < 2; i++)
        #pragma unroll
        for (int j = 0; j < 2; j++)
            wmma::fill_fragment(cacc[i][j], 0.0f);

    auto stage = [&](int bsel, const float4& p0, const float4& p1, const float4& vv) {
        __nv_bfloat16* Ah = (__nv_bfloat16*)(smem_raw + bsel*BUF_BYTES);
        __nv_bfloat16* Al = Ah + BM*LDA;
        __nv_bfloat16* Bh = (__nv_bfloat16*)(smem_raw + bsel*BUF_BYTES + 2*A_BYTES);
        __nv_bfloat16* Bl = Bh + BK*LDB;
        bf16_split_pair(Ah, Al, aRow0*LDA + aCol0,     p0.x, p0.y);
        bf16_split_pair(Ah, Al, aRow0*LDA + aCol0 + 2, p0.z, p0.w);
        bf16_split_pair(Ah, Al, aRow1*LDA + aCol1,     p1.x, p1.y);
        bf16_split_pair(Ah, Al, aRow1*LDA + aCol1 + 2, p1.z, p1.w);
        bf16_split_pair(Bh, Bl, vRow*LDB + vCol,       vv.x, vv.y);
        bf16_split_pair(Bh, Bl, vRow*LDB + vCol + 2,   vv.z, vv.w);
    };

    {   // prologue
        float4 p0 = *(const float4*)(Pb + (size_t)aRow0 * Sc + aCol0);
        float4 p1 = *(const float4*)(Pb + (size_t)aRow1 * Sc + aCol1);
        float4 vv = *(const float4*)(Vb + (size_t)vRow * Dc + vCol);
        stage(0, p0, p1, vv);
    }
    __syncthreads();

    int buf = 0;
    for (int k0 = BK; k0 <= Sc; k0 += BK) {
        float4 p0, p1, vv;
        const bool more = (k0 < Sc);
        if (more) {
            p0 = *(const float4*)(Pb + (size_t)aRow0 * Sc + k0 + aCol0);
            p1 = *(const float4*)(Pb + (size_t)aRow1 * Sc + k0 + aCol1);
            vv = *(const float4*)(Vb + (size_t)(k0 + vRow) * Dc + vCol);
        }
        {
            const __nv_bfloat16* Ah = (const __nv_bfloat16*)(smem_raw + buf*BUF_BYTES);
            const __nv_bfloat16* Al = Ah + BM*LDA;
            const __nv_bfloat16* Bh = (const __nv_bfloat16*)(smem_raw + buf*BUF_BYTES + 2*A_BYTES);
            const __nv_bfloat16* Bl = Bh + BK*LDB;

            wmma::fragment<wmma::matrix_a, 16, 16, 16, __nv_bfloat16, wmma::row_major> ah[2], al[2];
            #pragma unroll
            for (int i = 0; i < 2; i++) {
                wmma::load_matrix_sync(ah[i], Ah + (wr*32 + i*16)*LDA, LDA);
                wmma::load_matrix_sync(al[i], Al + (wr*32 + i*16)*LDA, LDA);
            }
            wmma::fragment<wmma::matrix_b, 16, 16, 16, __nv_bfloat16, wmma::row_major> bh[2], bl[2];
            #pragma unroll
            for (int j = 0; j < 2; j++) {
                wmma::load_matrix_sync(bh[j], Bh + wc*32 + j*16, LDB);
                wmma::load_matrix_sync(bl[j], Bl + wc*32 + j*16, LDB);
            }
            // term-major over 4 accumulators
            #pragma unroll
            for (int j = 0; j < 2; j++)
                #pragma unroll
                for (int i = 0; i < 2; i++)
                    wmma::mma_sync(cacc[i][j], ah[i], bh[j], cacc[i][j]);
            #pragma unroll
            for (int j = 0; j < 2; j++)
                #pragma unroll
                for (int i = 0; i < 2; i++)
                    wmma::mma_sync(cacc[i][j], ah[i], bl[j], cacc[i][j]);
            #pragma unroll
            for (int j = 0; j < 2; j++)
                #pragma unroll
                for (int i = 0; i < 2; i++)
                    wmma::mma_sync(cacc[i][j], al[i], bh[j], cacc[i][j]);
        }
        if (more) {
            stage(buf ^ 1, p0, p1, vv);
            __syncthreads();
            buf ^= 1;
        }
    }

    // epilogue: store fragments directly to gmem (row-major, ldm = Dc)
    float* Cg = ctx + ((size_t)(b*Sc + blockIdx.x*BM + wr*32)) * Dc + h*DKc + wc*32;
    #pragma unroll
    for (int i = 0; i < 2; i++)
        #pragma unroll
        for (int j = 0; j < 2; j++)
            wmma::store_matrix_sync(Cg + (size_t)(i*16)*Dc + j*16,
                                    cacc[i][j], Dc, wmma::mem_row_major);
}

// ---------------------------------------------------------------------------
// LayerNorm (single input, residual pre-added by GEMM epilogue)
// ---------------------------------------------------------------------------
__global__ __launch_bounds__(256)
void ln_rows(const float* __restrict__ X,
             const float* __restrict__ g, const float* __restrict__ be,
             float* __restrict__ out)
{
    __shared__ float ws[8], wq[8];
    const size_t base = (size_t)blockIdx.x * Dc;
    const int tid  = threadIdx.x;
    const int lane = tid & 31;
    const int wid  = tid >> 5;

    float v[4];
    float s = 0.f, sq = 0.f;
    #pragma unroll
    for (int t = 0; t < 4; t++) {
        int i = tid + 256*t;
        float val = X[base+i];
        v[t] = val; s += val; sq += val*val;
    }
    #pragma unroll
    for (int o = 16; o > 0; o >>= 1) {
        s  += __shfl_xor_sync(0xffffffffu, s,  o);
        sq += __shfl_xor_sync(0xffffffffu, sq, o);
    }
    if (lane == 0) { ws[wid] = s; wq[wid] = sq; }
    __syncthreads();
    s = ws[0]; sq = wq[0];
    #pragma unroll
    for (int i = 1; i < 8; i++) { s += ws[i]; sq += wq[i]; }

    const float mean = s * (1.f/Dc);
    const float var  = sq * (1.f/Dc) - mean*mean;
    const float inv  = rsqrtf(var + EPSc);
    #pragma unroll
    for (int t = 0; t < 4; t++) {
        int i = tid + 256*t;
        out[base+i] = (v[t] - mean) * inv * g[i] + be[i];
    }
}

// ---------------------------------------------------------------------------
// Launch
// ---------------------------------------------------------------------------
extern "C" void kernel_launch(void* const* d_in, const int* in_sizes, int n_in,
                              void* d_out, int out_size)
{
    const float* x   = (const float*)d_in[0];
    const int*   mask= (const int*)  d_in[1];
    const float* Wq  = (const float*)d_in[2];  const float* bq = (const float*)d_in[3];
    const float* Wk  = (const float*)d_in[4];  const float* bk = (const float*)d_in[5];
    const float* Wv  = (const float*)d_in[6];  const float* bv = (const float*)d_in[7];
    const float* Wo  = (const float*)d_in[8];  const float* bo = (const float*)d_in[9];
    const float* g1  = (const float*)d_in[10]; const float* be1= (const float*)d_in[11];
    const float* W1  = (const float*)d_in[12]; const float* b1 = (const float*)d_in[13];
    const float* W2  = (const float*)d_in[14]; const float* b2 = (const float*)d_in[15];
    const float* g2  = (const float*)d_in[16]; const float* be2= (const float*)d_in[17];

    float* out   = (float*)d_out;
    float* attnP = out + (size_t)Mc * Dc;   // attention probs region of d_out

    float *q, *k, *v, *ctx, *t0, *hbuf, *ff;
    cudaGetSymbolAddress((void**)&q,    g_q);
    cudaGetSymbolAddress((void**)&k,    g_k);
    cudaGetSymbolAddress((void**)&v,    g_v);
    cudaGetSymbolAddress((void**)&ctx,  g_ctx);
    cudaGetSymbolAddress((void**)&t0,   g_t0);
    cudaGetSymbolAddress((void**)&hbuf, g_h);
    cudaGetSymbolAddress((void**)&ff,   g_ff);

    dim3 gD  (Dc/128,  Mc/128);      // N=1024 gemms
    dim3 gQKV(Dc/128,  Mc/128, 3);   // fused QKV
    dim3 gFF (FFc/128, Mc/128);      // N=4096 gemm

    // QKV projections (single launch, z-indexed, bf16x3 tensor path)
    sgemm_qkv<<<gQKV, 256>>>(x, Wq, bq, Wk, bk, Wv, bv, q, k, v);

    // scores -> d_out attn region (raw, bf16x3 tensor path), softmax in-place
    attn_scores<<<dim3(Sc/128, Sc/128, Bc*Hc), 256>>>(q, k, mask, attnP);
    softmax_rows<<<Bc*Hc*Sc, 256>>>(attnP);

    // ctx = attn @ V (bf16x3 tensor path)
    attn_ctx<<<dim3(Sc/128, Bc*Hc), 256>>>(attnP, v, ctx);

    // output projection + residual (fused) -> t0 = ctx@Wo + bo + x, then LN
    sgemm_bias<false, true ><<<gD, 256>>>(ctx, Wo, bo, x, t0, Dc, Dc);
    ln_rows<<<Mc, 256>>>(t0, g1, be1, hbuf);

    // FFN: ff = relu(h@W1 + b1); t0 = ff@W2 + b2 + h (fused residual); LN
    sgemm_bias<true,  false><<<gFF, 256>>>(hbuf, W1, b1, nullptr, ff, FFc, Dc);
    sgemm_bias<false, true ><<<gD, 256>>>(ff,   W2, b2, hbuf,    t0, Dc, FFc);
    ln_rows<<<Mc, 256>>>(t0, g2, be2, out);
}